// round 1
// baseline (speedup 1.0000x reference)
#include <cuda_runtime.h>
#include <math.h>

#define D     256
#define D4    64
#define MAX_NSAMP  50000
#define MAX_NTOTAL 200000
#define MAX_E      1600000

// ---------------- scratch (static device globals; no allocation) -------------
__device__ float g_feat[MAX_NSAMP * D];       // blended features [N_SAMP, 256]
__device__ int   g_hist[MAX_NSAMP];
__device__ int   g_cursor[MAX_NSAMP];
__device__ int   g_rowStart[MAX_NSAMP + 1];
__device__ int   g_winner[MAX_NTOTAL];        // last sampled occurrence per buffer row
__device__ int   g_ecol[MAX_E];
__device__ float g_eval[MAX_E];

// ---------------- init: zero hist/cursor, winner=-1 --------------------------
__global__ void k_init(int nsamp, int ntotal) {
    int i = blockIdx.x * blockDim.x + threadIdx.x;
    if (i < nsamp) { g_hist[i] = 0; g_cursor[i] = 0; }
    if (i < ntotal) g_winner[i] = -1;
}

// ---------------- histogram of adj_row ---------------------------------------
__global__ void k_hist(const int* __restrict__ row, int E) {
    int i = blockIdx.x * blockDim.x + threadIdx.x;
    if (i < E) atomicAdd(&g_hist[row[i]], 1);
}

// ---------------- winner = last occurrence index per buffer row ---------------
__global__ void k_winner(const int* __restrict__ nodes, int n) {
    int i = blockIdx.x * blockDim.x + threadIdx.x;
    if (i < n) atomicMax(&g_winner[nodes[i]], i);
}

// ---------------- exclusive scan of hist -> rowStart (single block) -----------
__global__ void k_scan(int n, int E) {
    __shared__ int s[1024];
    int t = threadIdx.x;
    int chunk = (n + 1023) >> 10;
    int start = t * chunk;
    int end = min(start + chunk, n);
    int sum = 0;
    for (int i = start; i < end; i++) sum += g_hist[i];
    s[t] = sum;
    __syncthreads();
    for (int off = 1; off < 1024; off <<= 1) {
        int v = (t >= off) ? s[t - off] : 0;
        __syncthreads();
        s[t] += v;
        __syncthreads();
    }
    int base = (t > 0) ? s[t - 1] : 0;
    for (int i = start; i < end; i++) { g_rowStart[i] = base; base += g_hist[i]; }
    if (t == 0) g_rowStart[n] = E;
}

// ---------------- scatter edges into row-sorted order -------------------------
__global__ void k_scatter(const int* __restrict__ row, const int* __restrict__ col,
                          const float* __restrict__ val, int E) {
    int i = blockIdx.x * blockDim.x + threadIdx.x;
    if (i < E) {
        int r = row[i];
        int p = g_rowStart[r] + atomicAdd(&g_cursor[r], 1);
        g_ecol[p] = col[i];
        g_eval[p] = val[i];
    }
}

// ---------------- SpMM + momentum blend + sampled-row buffer update -----------
// One 64-thread CTA per sampled row; each thread owns one float4 of the row.
__global__ void k_spmm(const float4* __restrict__ x4, const int* __restrict__ nodes,
                       const float4* __restrict__ y4, float4* __restrict__ newY4,
                       int nsamp) {
    int r = blockIdx.x;
    if (r >= nsamp) return;
    int t = threadIdx.x;
    int e = g_rowStart[r];
    int end = g_rowStart[r + 1];
    float4 acc = make_float4(0.f, 0.f, 0.f, 0.f);
    for (; e < end; e++) {
        int   c = g_ecol[e];
        float v = g_eval[e];
        float4 xv = x4[(size_t)c * D4 + t];
        acc.x = fmaf(v, xv.x, acc.x);
        acc.y = fmaf(v, xv.y, acc.y);
        acc.z = fmaf(v, xv.z, acc.z);
        acc.w = fmaf(v, xv.w, acc.w);
    }
    int node = nodes[r];
    float4 yv = y4[(size_t)node * D4 + t];
    float4 g;
    g.x = fmaf(0.1f, acc.x, 0.9f * yv.x);
    g.y = fmaf(0.1f, acc.y, 0.9f * yv.y);
    g.z = fmaf(0.1f, acc.z, 0.9f * yv.z);
    g.w = fmaf(0.1f, acc.w, 0.9f * yv.w);
    ((float4*)g_feat)[(size_t)r * D4 + t] = g;
    if (g_winner[node] == r) newY4[(size_t)node * D4 + t] = g;  // last occurrence wins
}

// ---------------- decay pass for all non-sampled buffer rows -------------------
__global__ void k_decay(const float4* __restrict__ y4, float4* __restrict__ newY4,
                        int ntotal) {
    int i = blockIdx.x * blockDim.x + threadIdx.x;
    if (i >= ntotal * D4) return;
    int rrow = i >> 6;
    if (g_winner[rrow] < 0) {
        float4 v = y4[i];
        v.x *= 0.9f; v.y *= 0.9f; v.z *= 0.9f; v.w *= 0.9f;
        newY4[i] = v;
    }
}

// ---------------- fused GEMM (feat @ W + b) -> ELU -> per-row norm -------------
// Block: 256 threads, tile TM=64 rows x full 256 cols.
// Thread t: ry = t>>5 (row octet), cx = t&31 (lane). Each thread: 8 rows x 8 cols
// (cols cx*4..cx*4+3 and 128+cx*4..+3). One warp covers a full 256-col row
// -> mean/var via shuffle reduction, no second pass.
#define TM 64
#define TK 16
__global__ __launch_bounds__(256) void k_gemm(
    const float* __restrict__ W, const float* __restrict__ bvec,
    const float* __restrict__ scale, const float* __restrict__ offset,
    float* __restrict__ out, int nsamp) {
    __shared__ float featS[TK][TM + 4];   // transposed [k][m], padded stride 68
    __shared__ float WS[TK][D];

    int t = threadIdx.x;
    int cx = t & 31;
    int ry = t >> 5;
    int rowBase = blockIdx.x * TM;

    float acc[8][8];
#pragma unroll
    for (int i = 0; i < 8; i++)
#pragma unroll
        for (int j = 0; j < 8; j++) acc[i][j] = 0.f;

    for (int k0 = 0; k0 < D; k0 += TK) {
        // stage feat tile (64 rows x 16 k), transposed into smem
        {
            int m  = t >> 2;
            int kk = (t & 3) * 4;
            int grow = rowBase + m;
            float4 fv = make_float4(0.f, 0.f, 0.f, 0.f);
            if (grow < nsamp)
                fv = *(const float4*)(g_feat + (size_t)grow * D + k0 + kk);
            featS[kk + 0][m] = fv.x;
            featS[kk + 1][m] = fv.y;
            featS[kk + 2][m] = fv.z;
            featS[kk + 3][m] = fv.w;
        }
        // stage W tile (16 k x 256 cols)
#pragma unroll
        for (int i = 0; i < 4; i++) {
            int q  = t + 256 * i;         // float4 index in [16][64]
            int kk = q >> 6;
            int c4 = q & 63;
            float4 wv = *(const float4*)(W + (size_t)(k0 + kk) * D + c4 * 4);
            *(float4*)&WS[kk][c4 * 4] = wv;
        }
        __syncthreads();

#pragma unroll
        for (int kk = 0; kk < TK; kk++) {
            float a[8], w[8];
            float4 a0 = *(float4*)&featS[kk][ry * 8];
            float4 a1 = *(float4*)&featS[kk][ry * 8 + 4];
            a[0] = a0.x; a[1] = a0.y; a[2] = a0.z; a[3] = a0.w;
            a[4] = a1.x; a[5] = a1.y; a[6] = a1.z; a[7] = a1.w;
            float4 w0 = *(float4*)&WS[kk][cx * 4];
            float4 w1 = *(float4*)&WS[kk][128 + cx * 4];
            w[0] = w0.x; w[1] = w0.y; w[2] = w0.z; w[3] = w0.w;
            w[4] = w1.x; w[5] = w1.y; w[6] = w1.z; w[7] = w1.w;
#pragma unroll
            for (int i = 0; i < 8; i++)
#pragma unroll
                for (int j = 0; j < 8; j++)
                    acc[i][j] = fmaf(a[i], w[j], acc[i][j]);
        }
        __syncthreads();
    }

    // epilogue: bias -> ELU -> per-row mean/var -> normalize -> store
    float bj[8], sj[8], oj[8];
#pragma unroll
    for (int j = 0; j < 8; j++) {
        int col = (j < 4) ? (cx * 4 + j) : (128 + cx * 4 + (j - 4));
        bj[j] = bvec[col];
        sj[j] = scale[col];
        oj[j] = offset[col];
    }

#pragma unroll
    for (int i = 0; i < 8; i++) {
        float sum = 0.f, ssq = 0.f;
#pragma unroll
        for (int j = 0; j < 8; j++) {
            float v = acc[i][j] + bj[j];
            v = (v > 0.f) ? v : expm1f(v);     // ELU(alpha=1)
            acc[i][j] = v;
            sum += v;
            ssq += v * v;
        }
#pragma unroll
        for (int o = 16; o > 0; o >>= 1) {
            sum += __shfl_xor_sync(0xffffffff, sum, o);
            ssq += __shfl_xor_sync(0xffffffff, ssq, o);
        }
        float mean = sum * (1.f / 256.f);
        float var  = ssq * (1.f / 256.f) - mean * mean + 1e-9f;
        float rinv = rsqrtf(var);
        int grow = rowBase + ry * 8 + i;
        if (grow < nsamp) {
            float4 o0, o1;
            o0.x = (acc[i][0] - mean) * sj[0] * rinv + oj[0];
            o0.y = (acc[i][1] - mean) * sj[1] * rinv + oj[1];
            o0.z = (acc[i][2] - mean) * sj[2] * rinv + oj[2];
            o0.w = (acc[i][3] - mean) * sj[3] * rinv + oj[3];
            o1.x = (acc[i][4] - mean) * sj[4] * rinv + oj[4];
            o1.y = (acc[i][5] - mean) * sj[5] * rinv + oj[5];
            o1.z = (acc[i][6] - mean) * sj[6] * rinv + oj[6];
            o1.w = (acc[i][7] - mean) * sj[7] * rinv + oj[7];
            *(float4*)(out + (size_t)grow * D + cx * 4)       = o0;
            *(float4*)(out + (size_t)grow * D + 128 + cx * 4) = o1;
        }
    }
}

// -----------------------------------------------------------------------------
extern "C" void kernel_launch(void* const* d_in, const int* in_sizes, int n_in,
                              void* d_out, int out_size) {
    const float* x        = (const float*)d_in[0];
    const int*   adj_row  = (const int*)d_in[1];
    const int*   adj_col  = (const int*)d_in[2];
    const float* adj_val  = (const float*)d_in[3];
    const int*   nodes    = (const int*)d_in[4];
    const float* y_buf    = (const float*)d_in[5];
    const float* W        = (const float*)d_in[6];
    const float* b        = (const float*)d_in[7];
    const float* scale    = (const float*)d_in[8];
    const float* offset   = (const float*)d_in[9];

    int E      = in_sizes[1];
    int nsamp  = in_sizes[4];
    int ntotal = in_sizes[5] / D;

    float* out  = (float*)d_out;
    float* newY = out + (size_t)nsamp * D;   // outputs concatenated: (out, new_y)

    k_init<<<(ntotal + 511) / 512, 512>>>(nsamp, ntotal);
    k_hist<<<(E + 255) / 256, 256>>>(adj_row, E);
    k_winner<<<(nsamp + 255) / 256, 256>>>(nodes, nsamp);
    k_scan<<<1, 1024>>>(nsamp, E);
    k_scatter<<<(E + 255) / 256, 256>>>(adj_row, adj_col, adj_val, E);
    k_spmm<<<nsamp, 64>>>((const float4*)x, nodes, (const float4*)y_buf,
                          (float4*)newY, nsamp);
    k_decay<<<(ntotal * D4 + 255) / 256, 256>>>((const float4*)y_buf,
                                                (float4*)newY, ntotal);
    k_gemm<<<(nsamp + TM - 1) / TM, 256>>>(W, b, scale, offset, out, nsamp);
}

// round 2
// speedup vs baseline: 1.1207x; 1.1207x over previous
#include <cuda_runtime.h>
#include <math.h>

#define D     256
#define D4    64
#define MAX_NSAMP  50000
#define MAX_NTOTAL 200000
#define MAX_E      1600000
#define SCAN_TPB   256
#define SCAN_EPB   2048            // elems per scan block (256 thr x 8)
#define MAX_SCAN_G ((MAX_NSAMP + SCAN_EPB - 1) / SCAN_EPB)

// ---------------- scratch (static device globals; no allocation) -------------
__device__ float g_feat[MAX_NSAMP * D];       // blended features [N_SAMP, 256]
__device__ int   g_hist[MAX_NSAMP];
__device__ int   g_cursor[MAX_NSAMP];
__device__ int   g_rowStart[MAX_NSAMP + 1];
__device__ int   g_winner[MAX_NTOTAL];        // last sampled occurrence per buffer row
__device__ int   g_ecol[MAX_E];
__device__ float g_eval[MAX_E];
__device__ int   g_psum[MAX_SCAN_G + 1];
__device__ int   g_poff[MAX_SCAN_G + 1];

// ---------------- init: zero hist/cursor, winner=-1 --------------------------
__global__ void k_init(int nsamp, int ntotal) {
    int i = blockIdx.x * blockDim.x + threadIdx.x;
    if (i < nsamp) { g_hist[i] = 0; g_cursor[i] = 0; }
    if (i < ntotal) g_winner[i] = -1;
}

// ---------------- histogram of adj_row + winner(last occurrence) -------------
__global__ void k_histwin(const int* __restrict__ row, int E,
                          const int* __restrict__ nodes, int nsamp) {
    int i = blockIdx.x * blockDim.x + threadIdx.x;
    if (i < E) atomicAdd(&g_hist[row[i]], 1);
    if (i < nsamp) atomicMax(&g_winner[nodes[i]], i);
}

// ---------------- two-level exclusive scan of g_hist -> g_rowStart -----------
__global__ void k_scanA(int n) {
    __shared__ int s[SCAN_TPB];
    int t = threadIdx.x;
    int base = blockIdx.x * SCAN_EPB + t * 8;
    int sum = 0;
#pragma unroll
    for (int j = 0; j < 8; j++) {
        int idx = base + j;
        if (idx < n) sum += g_hist[idx];
    }
    s[t] = sum;
    __syncthreads();
    for (int o = SCAN_TPB >> 1; o > 0; o >>= 1) {
        if (t < o) s[t] += s[t + o];
        __syncthreads();
    }
    if (t == 0) g_psum[blockIdx.x] = s[0];
}

__global__ void k_scanB(int G, int n, int E) {
    // tiny: serial exclusive scan of G (~25) partials by one thread
    if (threadIdx.x == 0) {
        int run = 0;
        for (int i = 0; i < G; i++) { g_poff[i] = run; run += g_psum[i]; }
        g_rowStart[n] = E;
    }
}

__global__ void k_scanC(int n) {
    __shared__ int ws[SCAN_TPB / 32];
    int t = threadIdx.x;
    int lane = t & 31, w = t >> 5;
    int base = blockIdx.x * SCAN_EPB + t * 8;
    int v[8];
    int sum = 0;
#pragma unroll
    for (int j = 0; j < 8; j++) {
        int idx = base + j;
        v[j] = (idx < n) ? g_hist[idx] : 0;
        sum += v[j];
    }
    // warp inclusive scan of per-thread sums
    int x = sum;
#pragma unroll
    for (int o = 1; o < 32; o <<= 1) {
        int y = __shfl_up_sync(0xffffffff, x, o);
        if (lane >= o) x += y;
    }
    if (lane == 31) ws[w] = x;
    __syncthreads();
    if (t == 0) {
        int r = 0;
#pragma unroll
        for (int i = 0; i < SCAN_TPB / 32; i++) { int q = ws[i]; ws[i] = r; r += q; }
    }
    __syncthreads();
    int excl = x - sum + ws[w];
    int run = g_poff[blockIdx.x] + excl;
#pragma unroll
    for (int j = 0; j < 8; j++) {
        int idx = base + j;
        if (idx < n) g_rowStart[idx] = run;
        run += v[j];
    }
}

// ---------------- scatter edges into row-sorted order -------------------------
__global__ void k_scatter(const int* __restrict__ row, const int* __restrict__ col,
                          const float* __restrict__ val, int E) {
    int i = blockIdx.x * blockDim.x + threadIdx.x;
    if (i < E) {
        int r = row[i];
        int p = g_rowStart[r] + atomicAdd(&g_cursor[r], 1);
        g_ecol[p] = col[i];
        g_eval[p] = val[i];
    }
}

// ---------------- fused SpMM(+blend+buffer-write) and decay --------------------
// Heterogeneous blocks: even blocks do 4 SpMM rows (64 threads/row), odd blocks
// stream a 1024-float4 decay slice. SpMM is L2-bound, decay is DRAM-bound ->
// interleaving overlaps the two bottlenecks inside one kernel (no streams).
__global__ __launch_bounds__(256) void k_spmm_decay(
    const float4* __restrict__ x4, const int* __restrict__ nodes,
    const float4* __restrict__ y4, float4* __restrict__ newY4,
    int nsamp, int ntotal, int spmmB, int decayB) {
    int b = blockIdx.x;
    int t = threadIdx.x;
    int mn = min(spmmB, decayB);
    int nInter = 2 * mn;
    int type, piece;
    if (b < nInter) { type = b & 1; piece = b >> 1; }
    else { type = (spmmB > decayB) ? 0 : 1; piece = mn + (b - nInter); }

    if (type == 1) {
        // ---- decay slice: 1024 consecutive float4 of the y buffer
        long long total = (long long)ntotal * D4;
        long long i0 = (long long)piece * 1024 + t;
#pragma unroll
        for (int j = 0; j < 4; j++) {
            long long i = i0 + j * 256;
            if (i < total) {
                int rrow = (int)(i >> 6);
                if (g_winner[rrow] < 0) {
                    float4 v = y4[i];
                    v.x *= 0.9f; v.y *= 0.9f; v.z *= 0.9f; v.w *= 0.9f;
                    newY4[i] = v;
                }
            }
        }
        return;
    }

    // ---- SpMM: 4 rows per block, 64 threads per row
    int r = piece * 4 + (t >> 6);
    if (r >= nsamp) return;
    int tt = t & 63;
    int e = g_rowStart[r];
    int end = g_rowStart[r + 1];
    float4 acc = make_float4(0.f, 0.f, 0.f, 0.f);
    // 4-way unroll: batch independent gathers for MLP
    for (; e + 4 <= end; e += 4) {
        int c0 = g_ecol[e],     c1 = g_ecol[e + 1];
        int c2 = g_ecol[e + 2], c3 = g_ecol[e + 3];
        float v0 = g_eval[e],     v1 = g_eval[e + 1];
        float v2 = g_eval[e + 2], v3 = g_eval[e + 3];
        float4 a0 = x4[(size_t)c0 * D4 + tt];
        float4 a1 = x4[(size_t)c1 * D4 + tt];
        float4 a2 = x4[(size_t)c2 * D4 + tt];
        float4 a3 = x4[(size_t)c3 * D4 + tt];
        acc.x = fmaf(v0, a0.x, acc.x); acc.y = fmaf(v0, a0.y, acc.y);
        acc.z = fmaf(v0, a0.z, acc.z); acc.w = fmaf(v0, a0.w, acc.w);
        acc.x = fmaf(v1, a1.x, acc.x); acc.y = fmaf(v1, a1.y, acc.y);
        acc.z = fmaf(v1, a1.z, acc.z); acc.w = fmaf(v1, a1.w, acc.w);
        acc.x = fmaf(v2, a2.x, acc.x); acc.y = fmaf(v2, a2.y, acc.y);
        acc.z = fmaf(v2, a2.z, acc.z); acc.w = fmaf(v2, a2.w, acc.w);
        acc.x = fmaf(v3, a3.x, acc.x); acc.y = fmaf(v3, a3.y, acc.y);
        acc.z = fmaf(v3, a3.z, acc.z); acc.w = fmaf(v3, a3.w, acc.w);
    }
    for (; e < end; e++) {
        int   c = g_ecol[e];
        float v = g_eval[e];
        float4 xv = x4[(size_t)c * D4 + tt];
        acc.x = fmaf(v, xv.x, acc.x);
        acc.y = fmaf(v, xv.y, acc.y);
        acc.z = fmaf(v, xv.z, acc.z);
        acc.w = fmaf(v, xv.w, acc.w);
    }
    int node = nodes[r];
    float4 yv = y4[(size_t)node * D4 + tt];
    float4 g;
    g.x = fmaf(0.1f, acc.x, 0.9f * yv.x);
    g.y = fmaf(0.1f, acc.y, 0.9f * yv.y);
    g.z = fmaf(0.1f, acc.z, 0.9f * yv.z);
    g.w = fmaf(0.1f, acc.w, 0.9f * yv.w);
    ((float4*)g_feat)[(size_t)r * D4 + tt] = g;
    if (g_winner[node] == r) newY4[(size_t)node * D4 + tt] = g;  // last occurrence wins
}

// ---------------- fused GEMM (feat @ W + b) -> ELU -> per-row norm -------------
#define TM 64
#define TK 16
__global__ __launch_bounds__(256) void k_gemm(
    const float* __restrict__ W, const float* __restrict__ bvec,
    const float* __restrict__ scale, const float* __restrict__ offset,
    float* __restrict__ out, int nsamp) {
    __shared__ float featS[TK][TM + 4];
    __shared__ float WS[TK][D];

    int t = threadIdx.x;
    int cx = t & 31;
    int ry = t >> 5;
    int rowBase = blockIdx.x * TM;

    float acc[8][8];
#pragma unroll
    for (int i = 0; i < 8; i++)
#pragma unroll
        for (int j = 0; j < 8; j++) acc[i][j] = 0.f;

    for (int k0 = 0; k0 < D; k0 += TK) {
        {
            int m  = t >> 2;
            int kk = (t & 3) * 4;
            int grow = rowBase + m;
            float4 fv = make_float4(0.f, 0.f, 0.f, 0.f);
            if (grow < nsamp)
                fv = *(const float4*)(g_feat + (size_t)grow * D + k0 + kk);
            featS[kk + 0][m] = fv.x;
            featS[kk + 1][m] = fv.y;
            featS[kk + 2][m] = fv.z;
            featS[kk + 3][m] = fv.w;
        }
#pragma unroll
        for (int i = 0; i < 4; i++) {
            int q  = t + 256 * i;
            int kk = q >> 6;
            int c4 = q & 63;
            float4 wv = *(const float4*)(W + (size_t)(k0 + kk) * D + c4 * 4);
            *(float4*)&WS[kk][c4 * 4] = wv;
        }
        __syncthreads();

#pragma unroll
        for (int kk = 0; kk < TK; kk++) {
            float a[8], w[8];
            float4 a0 = *(float4*)&featS[kk][ry * 8];
            float4 a1 = *(float4*)&featS[kk][ry * 8 + 4];
            a[0] = a0.x; a[1] = a0.y; a[2] = a0.z; a[3] = a0.w;
            a[4] = a1.x; a[5] = a1.y; a[6] = a1.z; a[7] = a1.w;
            float4 w0 = *(float4*)&WS[kk][cx * 4];
            float4 w1 = *(float4*)&WS[kk][128 + cx * 4];
            w[0] = w0.x; w[1] = w0.y; w[2] = w0.z; w[3] = w0.w;
            w[4] = w1.x; w[5] = w1.y; w[6] = w1.z; w[7] = w1.w;
#pragma unroll
            for (int i = 0; i < 8; i++)
#pragma unroll
                for (int j = 0; j < 8; j++)
                    acc[i][j] = fmaf(a[i], w[j], acc[i][j]);
        }
        __syncthreads();
    }

    float bj[8], sj[8], oj[8];
#pragma unroll
    for (int j = 0; j < 8; j++) {
        int col = (j < 4) ? (cx * 4 + j) : (128 + cx * 4 + (j - 4));
        bj[j] = bvec[col];
        sj[j] = scale[col];
        oj[j] = offset[col];
    }

#pragma unroll
    for (int i = 0; i < 8; i++) {
        float sum = 0.f, ssq = 0.f;
#pragma unroll
        for (int j = 0; j < 8; j++) {
            float v = acc[i][j] + bj[j];
            v = (v > 0.f) ? v : expm1f(v);     // ELU(alpha=1)
            acc[i][j] = v;
            sum += v;
            ssq += v * v;
        }
#pragma unroll
        for (int o = 16; o > 0; o >>= 1) {
            sum += __shfl_xor_sync(0xffffffff, sum, o);
            ssq += __shfl_xor_sync(0xffffffff, ssq, o);
        }
        float mean = sum * (1.f / 256.f);
        float var  = ssq * (1.f / 256.f) - mean * mean + 1e-9f;
        float rinv = rsqrtf(var);
        int grow = rowBase + ry * 8 + i;
        if (grow < nsamp) {
            float4 o0, o1;
            o0.x = (acc[i][0] - mean) * sj[0] * rinv + oj[0];
            o0.y = (acc[i][1] - mean) * sj[1] * rinv + oj[1];
            o0.z = (acc[i][2] - mean) * sj[2] * rinv + oj[2];
            o0.w = (acc[i][3] - mean) * sj[3] * rinv + oj[3];
            o1.x = (acc[i][4] - mean) * sj[4] * rinv + oj[4];
            o1.y = (acc[i][5] - mean) * sj[5] * rinv + oj[5];
            o1.z = (acc[i][6] - mean) * sj[6] * rinv + oj[6];
            o1.w = (acc[i][7] - mean) * sj[7] * rinv + oj[7];
            *(float4*)(out + (size_t)grow * D + cx * 4)       = o0;
            *(float4*)(out + (size_t)grow * D + 128 + cx * 4) = o1;
        }
    }
}

// -----------------------------------------------------------------------------
extern "C" void kernel_launch(void* const* d_in, const int* in_sizes, int n_in,
                              void* d_out, int out_size) {
    const float* x        = (const float*)d_in[0];
    const int*   adj_row  = (const int*)d_in[1];
    const int*   adj_col  = (const int*)d_in[2];
    const float* adj_val  = (const float*)d_in[3];
    const int*   nodes    = (const int*)d_in[4];
    const float* y_buf    = (const float*)d_in[5];
    const float* W        = (const float*)d_in[6];
    const float* b        = (const float*)d_in[7];
    const float* scale    = (const float*)d_in[8];
    const float* offset   = (const float*)d_in[9];

    int E      = in_sizes[1];
    int nsamp  = in_sizes[4];
    int ntotal = in_sizes[5] / D;

    float* out  = (float*)d_out;
    float* newY = out + (size_t)nsamp * D;   // outputs concatenated: (out, new_y)

    int G = (nsamp + SCAN_EPB - 1) / SCAN_EPB;
    int spmmB  = (nsamp + 3) / 4;
    int decayB = (ntotal * D4 + 1023) / 1024;

    k_init<<<(ntotal + 511) / 512, 512>>>(nsamp, ntotal);
    k_histwin<<<(E + 255) / 256, 256>>>(adj_row, E, nodes, nsamp);
    k_scanA<<<G, SCAN_TPB>>>(nsamp);
    k_scanB<<<1, 32>>>(G, nsamp, E);
    k_scanC<<<G, SCAN_TPB>>>(nsamp);
    k_scatter<<<(E + 255) / 256, 256>>>(adj_row, adj_col, adj_val, E);
    k_spmm_decay<<<spmmB + decayB, 256>>>((const float4*)x, nodes,
                                          (const float4*)y_buf, (float4*)newY,
                                          nsamp, ntotal, spmmB, decayB);
    k_gemm<<<(nsamp + TM - 1) / TM, 256>>>(W, b, scale, offset, out, nsamp);
}

// round 4
// speedup vs baseline: 1.2446x; 1.1105x over previous
#include <cuda_runtime.h>
#include <cuda_bf16.h>
#include <math.h>
#include <cstdint>

#define D     256
#define D4    64
#define MAX_NSAMP  50000
#define MAX_NSRC   50000
#define MAX_NTOTAL 200000
#define MAX_E      1600000
#define SCAN_TPB   256
#define SCAN_EPB   2048
#define MAX_SCAN_G ((MAX_NSAMP + SCAN_EPB - 1) / SCAN_EPB)

// ---------------- scratch (static device globals; no allocation) -------------
__device__ __nv_bfloat16 g_xbf[MAX_NSRC * D];        // x in bf16
__device__ __nv_bfloat16 g_feat_hi[MAX_NSAMP * D];   // feat split hi
__device__ __nv_bfloat16 g_feat_lo[MAX_NSAMP * D];   // feat split lo
__device__ __nv_bfloat16 g_wt_hi[D * D];             // W^T split hi  [n][k]
__device__ __nv_bfloat16 g_wt_lo[D * D];             // W^T split lo
__device__ int   g_hist[MAX_NSAMP];
__device__ int   g_cursor[MAX_NSAMP];
__device__ int   g_rowStart[MAX_NSAMP + 1];
__device__ int   g_winner[MAX_NTOTAL];
__device__ int2  g_edge[MAX_E];                      // packed (col, val bits)
__device__ int   g_psum[MAX_SCAN_G + 1];
__device__ int   g_poff[MAX_SCAN_G + 1];

// ============================ prep / sort kernels ============================
__global__ void k_init(int nsamp, int ntotal) {
    int i = blockIdx.x * blockDim.x + threadIdx.x;
    if (i < nsamp) { g_hist[i] = 0; g_cursor[i] = 0; }
    if (i < ntotal) g_winner[i] = -1;
}

// heterogeneous prep: [0,convB) convert x->bf16, [convB,convB+wB) split W^T,
// rest: edge histogram + winner
__global__ void k_prep(const float* __restrict__ x, const float* __restrict__ W,
                       const int* __restrict__ row, int E,
                       const int* __restrict__ nodes, int nsamp,
                       int nsrc, int convB, int wB) {
    int b = blockIdx.x;
    int t = threadIdx.x;
    if (b < convB) {
        long long total = (long long)nsrc * D4;
        long long i0 = (long long)b * 1024 + t;
        const float4* x4 = (const float4*)x;
#pragma unroll
        for (int j = 0; j < 4; j++) {
            long long i = i0 + j * 256;
            if (i < total) {
                float4 v = x4[i];
                __nv_bfloat162 p0 = __float22bfloat162_rn(make_float2(v.x, v.y));
                __nv_bfloat162 p1 = __float22bfloat162_rn(make_float2(v.z, v.w));
                uint2 u;
                u.x = *(uint32_t*)&p0;
                u.y = *(uint32_t*)&p1;
                ((uint2*)g_xbf)[i] = u;
            }
        }
        return;
    }
    if (b < convB + wB) {
        int i = (b - convB) * 256 + t;   // i over D*D
        if (i < D * D) {
            int k = i >> 8, n = i & 255;
            float w = W[k * D + n];
            __nv_bfloat16 hi = __float2bfloat16_rn(w);
            __nv_bfloat16 lo = __float2bfloat16_rn(w - __bfloat162float(hi));
            g_wt_hi[n * D + k] = hi;
            g_wt_lo[n * D + k] = lo;
        }
        return;
    }
    int i = (b - convB - wB) * 256 + t;
    if (i < E) atomicAdd(&g_hist[row[i]], 1);
    if (i < nsamp) atomicMax(&g_winner[nodes[i]], i);
}

// two-level exclusive scan
__global__ void k_scanA(int n) {
    __shared__ int s[SCAN_TPB];
    int t = threadIdx.x;
    int base = blockIdx.x * SCAN_EPB + t * 8;
    int sum = 0;
#pragma unroll
    for (int j = 0; j < 8; j++) { int idx = base + j; if (idx < n) sum += g_hist[idx]; }
    s[t] = sum;
    __syncthreads();
    for (int o = SCAN_TPB >> 1; o > 0; o >>= 1) {
        if (t < o) s[t] += s[t + o];
        __syncthreads();
    }
    if (t == 0) g_psum[blockIdx.x] = s[0];
}
__global__ void k_scanB(int G, int n, int E) {
    if (threadIdx.x == 0) {
        int run = 0;
        for (int i = 0; i < G; i++) { g_poff[i] = run; run += g_psum[i]; }
        g_rowStart[n] = E;
    }
}
__global__ void k_scanC(int n) {
    __shared__ int ws[SCAN_TPB / 32];
    int t = threadIdx.x, lane = t & 31, w = t >> 5;
    int base = blockIdx.x * SCAN_EPB + t * 8;
    int v[8], sum = 0;
#pragma unroll
    for (int j = 0; j < 8; j++) {
        int idx = base + j;
        v[j] = (idx < n) ? g_hist[idx] : 0;
        sum += v[j];
    }
    int x = sum;
#pragma unroll
    for (int o = 1; o < 32; o <<= 1) {
        int y = __shfl_up_sync(0xffffffff, x, o);
        if (lane >= o) x += y;
    }
    if (lane == 31) ws[w] = x;
    __syncthreads();
    if (t == 0) {
        int r = 0;
#pragma unroll
        for (int i = 0; i < SCAN_TPB / 32; i++) { int q = ws[i]; ws[i] = r; r += q; }
    }
    __syncthreads();
    int run = g_poff[blockIdx.x] + (x - sum) + ws[w];
#pragma unroll
    for (int j = 0; j < 8; j++) {
        int idx = base + j;
        if (idx < n) g_rowStart[idx] = run;
        run += v[j];
    }
}

__global__ void k_scatter(const int* __restrict__ row, const int* __restrict__ col,
                          const float* __restrict__ val, int E) {
    int i = blockIdx.x * blockDim.x + threadIdx.x;
    if (i < E) {
        int r = row[i];
        int p = g_rowStart[r] + atomicAdd(&g_cursor[r], 1);
        int2 e;
        e.x = col[i];
        e.y = __float_as_int(val[i]);
        g_edge[p] = e;
    }
}

// ================= fused SpMM (bf16 gather) + blend + decay ==================
__global__ __launch_bounds__(256) void k_spmm_decay(
    const int* __restrict__ nodes,
    const float4* __restrict__ y4, float4* __restrict__ newY4,
    int nsamp, int ntotal, int spmmB, int decayB) {
    int b = blockIdx.x;
    int t = threadIdx.x;
    int mn = min(spmmB, decayB);
    int nInter = 2 * mn;
    int type, piece;
    if (b < nInter) { type = b & 1; piece = b >> 1; }
    else { type = (spmmB > decayB) ? 0 : 1; piece = mn + (b - nInter); }

    if (type == 1) {
        long long total = (long long)ntotal * D4;
        long long i0 = (long long)piece * 1024 + t;
#pragma unroll
        for (int j = 0; j < 4; j++) {
            long long i = i0 + j * 256;
            if (i < total) {
                int rrow = (int)(i >> 6);
                if (g_winner[rrow] < 0) {
                    float4 v = y4[i];
                    v.x *= 0.9f; v.y *= 0.9f; v.z *= 0.9f; v.w *= 0.9f;
                    newY4[i] = v;
                }
            }
        }
        return;
    }

    int r = piece * 4 + (t >> 6);
    if (r >= nsamp) return;
    int tt = t & 63;
    int e = g_rowStart[r];
    int end = g_rowStart[r + 1];
    const uint2* xb = (const uint2*)g_xbf;
    float4 acc = make_float4(0.f, 0.f, 0.f, 0.f);
#pragma unroll 1
    for (; e + 4 <= end; e += 4) {
        int2 e0 = g_edge[e],     e1 = g_edge[e + 1];
        int2 e2 = g_edge[e + 2], e3 = g_edge[e + 3];
        uint2 u0 = xb[(size_t)e0.x * D4 + tt];
        uint2 u1 = xb[(size_t)e1.x * D4 + tt];
        uint2 u2 = xb[(size_t)e2.x * D4 + tt];
        uint2 u3 = xb[(size_t)e3.x * D4 + tt];
        float v0 = __int_as_float(e0.y), v1 = __int_as_float(e1.y);
        float v2 = __int_as_float(e2.y), v3 = __int_as_float(e3.y);
        float2 a, c;
        a = __bfloat1622float2(*(__nv_bfloat162*)&u0.x);
        c = __bfloat1622float2(*(__nv_bfloat162*)&u0.y);
        acc.x = fmaf(v0, a.x, acc.x); acc.y = fmaf(v0, a.y, acc.y);
        acc.z = fmaf(v0, c.x, acc.z); acc.w = fmaf(v0, c.y, acc.w);
        a = __bfloat1622float2(*(__nv_bfloat162*)&u1.x);
        c = __bfloat1622float2(*(__nv_bfloat162*)&u1.y);
        acc.x = fmaf(v1, a.x, acc.x); acc.y = fmaf(v1, a.y, acc.y);
        acc.z = fmaf(v1, c.x, acc.z); acc.w = fmaf(v1, c.y, acc.w);
        a = __bfloat1622float2(*(__nv_bfloat162*)&u2.x);
        c = __bfloat1622float2(*(__nv_bfloat162*)&u2.y);
        acc.x = fmaf(v2, a.x, acc.x); acc.y = fmaf(v2, a.y, acc.y);
        acc.z = fmaf(v2, c.x, acc.z); acc.w = fmaf(v2, c.y, acc.w);
        a = __bfloat1622float2(*(__nv_bfloat162*)&u3.x);
        c = __bfloat1622float2(*(__nv_bfloat162*)&u3.y);
        acc.x = fmaf(v3, a.x, acc.x); acc.y = fmaf(v3, a.y, acc.y);
        acc.z = fmaf(v3, c.x, acc.z); acc.w = fmaf(v3, c.y, acc.w);
    }
    for (; e < end; e++) {
        int2 eg = g_edge[e];
        uint2 u = xb[(size_t)eg.x * D4 + tt];
        float v = __int_as_float(eg.y);
        float2 a = __bfloat1622float2(*(__nv_bfloat162*)&u.x);
        float2 c = __bfloat1622float2(*(__nv_bfloat162*)&u.y);
        acc.x = fmaf(v, a.x, acc.x); acc.y = fmaf(v, a.y, acc.y);
        acc.z = fmaf(v, c.x, acc.z); acc.w = fmaf(v, c.y, acc.w);
    }
    int node = nodes[r];
    float4 yv = y4[(size_t)node * D4 + tt];
    float4 g;
    g.x = fmaf(0.1f, acc.x, 0.9f * yv.x);
    g.y = fmaf(0.1f, acc.y, 0.9f * yv.y);
    g.z = fmaf(0.1f, acc.z, 0.9f * yv.z);
    g.w = fmaf(0.1f, acc.w, 0.9f * yv.w);
    __nv_bfloat16 hx = __float2bfloat16_rn(g.x), hy = __float2bfloat16_rn(g.y);
    __nv_bfloat16 hz = __float2bfloat16_rn(g.z), hw = __float2bfloat16_rn(g.w);
    __nv_bfloat16 lx = __float2bfloat16_rn(g.x - __bfloat162float(hx));
    __nv_bfloat16 ly = __float2bfloat16_rn(g.y - __bfloat162float(hy));
    __nv_bfloat16 lz = __float2bfloat16_rn(g.z - __bfloat162float(hz));
    __nv_bfloat16 lw = __float2bfloat16_rn(g.w - __bfloat162float(hw));
    uint2 uh, ul;
    __nv_bfloat162 t0 = __halves2bfloat162(hx, hy);
    __nv_bfloat162 t1 = __halves2bfloat162(hz, hw);
    uh.x = *(uint32_t*)&t0; uh.y = *(uint32_t*)&t1;
    t0 = __halves2bfloat162(lx, ly);
    t1 = __halves2bfloat162(lz, lw);
    ul.x = *(uint32_t*)&t0; ul.y = *(uint32_t*)&t1;
    ((uint2*)g_feat_hi)[(size_t)r * D4 + tt] = uh;
    ((uint2*)g_feat_lo)[(size_t)r * D4 + tt] = ul;
    if (g_winner[node] == r) newY4[(size_t)node * D4 + tt] = g;
}

// ========== HMMA GEMM via mma.sync m16n8k16 bf16, 3-term split ===============
// Block: 256 thr (8 warps), tile 64 rows x 256 cols. Warp w owns N strip w*32.
// BK=16. Smem row stride 24 bf16 (48B, bank step 12 -> conflict-free frags).
#define AST 24                       // A/B smem stride in bf16
#define SM_A_HI 0                    // 64*24*2  = 3072
#define SM_A_LO 3072
#define SM_B_HI 6144                 // 256*24*2 = 12288
#define SM_B_LO 18432
#define SM_GEMM_TOTAL 30720
// epilogue aliases A region (k-loop done): rowsum[64][8], rowssq[64][8], mean+rstd
#define EP_SUM  0
#define EP_SSQ  2048
#define EP_MEAN 4096
#define EP_RSTD 4352

__device__ __forceinline__ void mma_bf16(float* c, uint32_t a0, uint32_t a1,
                                         uint32_t a2, uint32_t a3,
                                         uint32_t b0, uint32_t b1) {
    asm volatile(
        "mma.sync.aligned.m16n8k16.row.col.f32.bf16.bf16.f32 "
        "{%0,%1,%2,%3}, {%4,%5,%6,%7}, {%8,%9}, {%0,%1,%2,%3};"
        : "+f"(c[0]), "+f"(c[1]), "+f"(c[2]), "+f"(c[3])
        : "r"(a0), "r"(a1), "r"(a2), "r"(a3), "r"(b0), "r"(b1));
}

__global__ __launch_bounds__(256) void k_gemm_mma(
    const float* __restrict__ bvec, const float* __restrict__ scale,
    const float* __restrict__ offset, float* __restrict__ out, int nsamp) {
    __shared__ char sm[SM_GEMM_TOTAL];
    int t = threadIdx.x;
    int warp = t >> 5, lane = t & 31;
    int lq = lane >> 2, lc = lane & 3;
    int wN = warp * 32;
    int rowBase = blockIdx.x * 64;

    float acc[4][4][4];
#pragma unroll
    for (int i = 0; i < 4; i++)
#pragma unroll
        for (int j = 0; j < 4; j++)
#pragma unroll
            for (int q = 0; q < 4; q++) acc[i][j][q] = 0.f;

    // gmem->smem indices
    int arow = t >> 2, ac4 = t & 3;          // A: one uint2 per thread
    int agrow = rowBase + arow;

    for (int kc = 0; kc < 16; kc++) {
        int k0 = kc * 16;
        // stage A (64 x 16) hi+lo
        {
            uint2 vh = make_uint2(0u, 0u), vl = make_uint2(0u, 0u);
            if (agrow < nsamp) {
                vh = *(const uint2*)&g_feat_hi[(size_t)agrow * D + k0 + ac4 * 4];
                vl = *(const uint2*)&g_feat_lo[(size_t)agrow * D + k0 + ac4 * 4];
            }
            *(uint2*)(sm + SM_A_HI + (arow * AST + ac4 * 4) * 2) = vh;
            *(uint2*)(sm + SM_A_LO + (arow * AST + ac4 * 4) * 2) = vl;
        }
        // stage B (256 x 16) hi+lo : 1024 uint2 -> 4 per thread
#pragma unroll
        for (int j = 0; j < 4; j++) {
            int i = t + j * 256;
            int n = i >> 2, c4 = i & 3;
            *(uint2*)(sm + SM_B_HI + (n * AST + c4 * 4) * 2) =
                *(const uint2*)&g_wt_hi[(size_t)n * D + k0 + c4 * 4];
            *(uint2*)(sm + SM_B_LO + (n * AST + c4 * 4) * 2) =
                *(const uint2*)&g_wt_lo[(size_t)n * D + c4 * 4 + k0];
        }
        __syncthreads();

        // B fragments (k16 x n8 per nf)
        uint32_t bh[4][2], bl[4][2];
#pragma unroll
        for (int nf = 0; nf < 4; nf++) {
            int n = wN + nf * 8 + lq;
            bh[nf][0] = *(uint32_t*)(sm + SM_B_HI + (n * AST + lc * 2) * 2);
            bh[nf][1] = *(uint32_t*)(sm + SM_B_HI + (n * AST + lc * 2 + 8) * 2);
            bl[nf][0] = *(uint32_t*)(sm + SM_B_LO + (n * AST + lc * 2) * 2);
            bl[nf][1] = *(uint32_t*)(sm + SM_B_LO + (n * AST + lc * 2 + 8) * 2);
        }
        {
            uint32_t ah[4][4];
#pragma unroll
            for (int mf = 0; mf < 4; mf++) {
                int r0 = mf * 16 + lq;
                ah[mf][0] = *(uint32_t*)(sm + SM_A_HI + (r0 * AST + lc * 2) * 2);
                ah[mf][1] = *(uint32_t*)(sm + SM_A_HI + ((r0 + 8) * AST + lc * 2) * 2);
                ah[mf][2] = *(uint32_t*)(sm + SM_A_HI + (r0 * AST + lc * 2 + 8) * 2);
                ah[mf][3] = *(uint32_t*)(sm + SM_A_HI + ((r0 + 8) * AST + lc * 2 + 8) * 2);
            }
#pragma unroll
            for (int mf = 0; mf < 4; mf++)
#pragma unroll
                for (int nf = 0; nf < 4; nf++) {
                    mma_bf16(acc[mf][nf], ah[mf][0], ah[mf][1], ah[mf][2], ah[mf][3],
                             bh[nf][0], bh[nf][1]);
                    mma_bf16(acc[mf][nf], ah[mf][0], ah[mf][1], ah[mf][2], ah[mf][3],
                             bl[nf][0], bl[nf][1]);
                }
        }
        {
            uint32_t al[4][4];
#pragma unroll
            for (int mf = 0; mf < 4; mf++) {
                int r0 = mf * 16 + lq;
                al[mf][0] = *(uint32_t*)(sm + SM_A_LO + (r0 * AST + lc * 2) * 2);
                al[mf][1] = *(uint32_t*)(sm + SM_A_LO + ((r0 + 8) * AST + lc * 2) * 2);
                al[mf][2] = *(uint32_t*)(sm + SM_A_LO + (r0 * AST + lc * 2 + 8) * 2);
                al[mf][3] = *(uint32_t*)(sm + SM_A_LO + ((r0 + 8) * AST + lc * 2 + 8) * 2);
            }
#pragma unroll
            for (int mf = 0; mf < 4; mf++)
#pragma unroll
                for (int nf = 0; nf < 4; nf++)
                    mma_bf16(acc[mf][nf], al[mf][0], al[mf][1], al[mf][2], al[mf][3],
                             bh[nf][0], bh[nf][1]);
        }
        __syncthreads();
    }

    // ---- epilogue: bias -> ELU (in regs) -> cross-warp row reduce -> norm ----
    float bb[4][2], ss[4][2], oo[4][2];
#pragma unroll
    for (int nf = 0; nf < 4; nf++) {
        int col = wN + nf * 8 + lc * 2;
        bb[nf][0] = bvec[col];   bb[nf][1] = bvec[col + 1];
        ss[nf][0] = scale[col];  ss[nf][1] = scale[col + 1];
        oo[nf][0] = offset[col]; oo[nf][1] = offset[col + 1];
    }

    float rs[4][2], rq[4][2];
#pragma unroll
    for (int mf = 0; mf < 4; mf++) { rs[mf][0] = rs[mf][1] = 0.f; rq[mf][0] = rq[mf][1] = 0.f; }
#pragma unroll
    for (int mf = 0; mf < 4; mf++)
#pragma unroll
        for (int nf = 0; nf < 4; nf++) {
            float v0 = acc[mf][nf][0] + bb[nf][0];
            float v1 = acc[mf][nf][1] + bb[nf][1];
            float v2 = acc[mf][nf][2] + bb[nf][0];
            float v3 = acc[mf][nf][3] + bb[nf][1];
            v0 = (v0 > 0.f) ? v0 : expm1f(v0);
            v1 = (v1 > 0.f) ? v1 : expm1f(v1);
            v2 = (v2 > 0.f) ? v2 : expm1f(v2);
            v3 = (v3 > 0.f) ? v3 : expm1f(v3);
            acc[mf][nf][0] = v0; acc[mf][nf][1] = v1;
            acc[mf][nf][2] = v2; acc[mf][nf][3] = v3;
            rs[mf][0] += v0 + v1; rq[mf][0] += v0 * v0 + v1 * v1;
            rs[mf][1] += v2 + v3; rq[mf][1] += v2 * v2 + v3 * v3;
        }
    // reduce within quad (lanes differing in lc)
#pragma unroll
    for (int mf = 0; mf < 4; mf++)
#pragma unroll
        for (int h = 0; h < 2; h++) {
            rs[mf][h] += __shfl_xor_sync(0xffffffff, rs[mf][h], 1);
            rs[mf][h] += __shfl_xor_sync(0xffffffff, rs[mf][h], 2);
            rq[mf][h] += __shfl_xor_sync(0xffffffff, rq[mf][h], 1);
            rq[mf][h] += __shfl_xor_sync(0xffffffff, rq[mf][h], 2);
        }
    __syncthreads();                          // all mma smem reads done -> safe to alias
    float* rowsum = (float*)(sm + EP_SUM);
    float* rowssq = (float*)(sm + EP_SSQ);
    if (lc == 0) {
#pragma unroll
        for (int mf = 0; mf < 4; mf++) {
            rowsum[(mf * 16 + lq) * 8 + warp]     = rs[mf][0];
            rowssq[(mf * 16 + lq) * 8 + warp]     = rq[mf][0];
            rowsum[(mf * 16 + 8 + lq) * 8 + warp] = rs[mf][1];
            rowssq[(mf * 16 + 8 + lq) * 8 + warp] = rq[mf][1];
        }
    }
    __syncthreads();
    float* meanA = (float*)(sm + EP_MEAN);
    float* rstdA = (float*)(sm + EP_RSTD);
    if (t < 64) {
        float s = 0.f, q = 0.f;
#pragma unroll
        for (int w = 0; w < 8; w++) { s += rowsum[t * 8 + w]; q += rowssq[t * 8 + w]; }
        float mean = s * (1.f / 256.f);
        float var  = q * (1.f / 256.f) - mean * mean + 1e-9f;
        meanA[t] = mean;
        rstdA[t] = rsqrtf(var);
    }
    __syncthreads();

#pragma unroll
    for (int mf = 0; mf < 4; mf++) {
        int rl = mf * 16 + lq;
        int rh = rl + 8;
        float mL = meanA[rl], rL = rstdA[rl];
        float mH = meanA[rh], rH = rstdA[rh];
        int gl = rowBase + rl, gh = rowBase + rh;
#pragma unroll
        for (int nf = 0; nf < 4; nf++) {
            int col = wN + nf * 8 + lc * 2;
            if (gl < nsamp) {
                float2 p;
                p.x = (acc[mf][nf][0] - mL) * ss[nf][0] * rL + oo[nf][0];
                p.y = (acc[mf][nf][1] - mL) * ss[nf][1] * rL + oo[nf][1];
                *(float2*)(out + (size_t)gl * D + col) = p;
            }
            if (gh < nsamp) {
                float2 p;
                p.x = (acc[mf][nf][2] - mH) * ss[nf][0] * rH + oo[nf][0];
                p.y = (acc[mf][nf][3] - mH) * ss[nf][1] * rH + oo[nf][1];
                *(float2*)(out + (size_t)gh * D + col) = p;
            }
        }
    }
}

// -----------------------------------------------------------------------------
extern "C" void kernel_launch(void* const* d_in, const int* in_sizes, int n_in,
                              void* d_out, int out_size) {
    const float* x        = (const float*)d_in[0];
    const int*   adj_row  = (const int*)d_in[1];
    const int*   adj_col  = (const int*)d_in[2];
    const float* adj_val  = (const float*)d_in[3];
    const int*   nodes    = (const int*)d_in[4];
    const float* y_buf    = (const float*)d_in[5];
    const float* W        = (const float*)d_in[6];
    const float* b        = (const float*)d_in[7];
    const float* scale    = (const float*)d_in[8];
    const float* offset   = (const float*)d_in[9];

    int E      = in_sizes[1];
    int nsamp  = in_sizes[4];
    int nsrc   = in_sizes[0] / D;
    int ntotal = in_sizes[5] / D;

    float* out  = (float*)d_out;
    float* newY = out + (size_t)nsamp * D;

    int G = (nsamp + SCAN_EPB - 1) / SCAN_EPB;
    int spmmB  = (nsamp + 3) / 4;
    int decayB = (ntotal * D4 + 1023) / 1024;
    int convB  = (nsrc * D4 + 1023) / 1024;
    int wB     = (D * D + 255) / 256;
    int histB  = (E + 255) / 256;

    k_init<<<(ntotal + 511) / 512, 512>>>(nsamp, ntotal);
    k_prep<<<convB + wB + histB, 256>>>(x, W, adj_row, E, nodes, nsamp, nsrc, convB, wB);
    k_scanA<<<G, SCAN_TPB>>>(nsamp);
    k_scanB<<<1, 32>>>(G, nsamp, E);
    k_scanC<<<G, SCAN_TPB>>>(nsamp);
    k_scatter<<<(E + 255) / 256, 256>>>(adj_row, adj_col, adj_val, E);
    k_spmm_decay<<<spmmB + decayB, 256>>>(nodes, (const float4*)y_buf, (float4*)newY,
                                          nsamp, ntotal, spmmB, decayB);
    k_gemm_mma<<<(nsamp + 63) / 64, 256>>>(b, scale, offset, out, nsamp);
}

// round 5
// speedup vs baseline: 1.4374x; 1.1549x over previous
#include <cuda_runtime.h>
#include <cuda_bf16.h>
#include <math.h>
#include <cstdint>

#define D     256
#define D4    64
#define D16   32                     // uint4 per 256-bf16 row
#define MAX_NSAMP  50000
#define MAX_NSRC   50000
#define MAX_NTOTAL 200000
#define MAX_E      1600000
#define SCAN_TPB   256
#define SCAN_EPB   2048

// ---------------- scratch (static device globals; no allocation) -------------
// Self-cleaning invariants (valid at entry of every kernel_launch call):
//   g_hist == 0 (zeroed by k_scatter), g_cursor == 0 (zeroed by k_scan),
//   g_winner == 0 (zeroed at end of k_gemm_mma; encoding: winner = idx+1, 0 = empty)
__device__ __nv_bfloat16 g_xbf[MAX_NSRC * D];
__device__ __nv_bfloat16 g_feat_hi[MAX_NSAMP * D];
__device__ __nv_bfloat16 g_feat_lo[MAX_NSAMP * D];
__device__ __nv_bfloat16 g_wt_hi[D * D];             // W^T hi  [n][k]
__device__ __nv_bfloat16 g_wt_lo[D * D];             // W^T lo
__device__ int   g_hist[MAX_NSAMP];
__device__ int   g_cursor[MAX_NSAMP];
__device__ int   g_rowStart[MAX_NSAMP + 1];
__device__ int   g_winner[MAX_NTOTAL];
__device__ int2  g_edge[MAX_E];

// ================= prep: x->bf16, W^T split, hist, winner ====================
__global__ void k_prep(const float* __restrict__ x, const float* __restrict__ W,
                       const int* __restrict__ row, int E,
                       const int* __restrict__ nodes, int nsamp,
                       int nsrc, int convB, int wB) {
    int b = blockIdx.x;
    int t = threadIdx.x;
    if (b < convB) {
        long long total = (long long)nsrc * D4;
        long long i0 = (long long)b * 1024 + t;
        const float4* x4 = (const float4*)x;
#pragma unroll
        for (int j = 0; j < 4; j++) {
            long long i = i0 + j * 256;
            if (i < total) {
                float4 v = x4[i];
                __nv_bfloat162 p0 = __floats2bfloat162_rn(v.x, v.y);
                __nv_bfloat162 p1 = __floats2bfloat162_rn(v.z, v.w);
                uint2 u;
                u.x = *(uint32_t*)&p0;
                u.y = *(uint32_t*)&p1;
                ((uint2*)g_xbf)[i] = u;
            }
        }
        return;
    }
    if (b < convB + wB) {
        int i = (b - convB) * 256 + t;
        if (i < D * D) {
            int k = i >> 8, n = i & 255;
            float w = W[k * D + n];
            __nv_bfloat16 hi = __float2bfloat16_rn(w);
            __nv_bfloat16 lo = __float2bfloat16_rn(w - __bfloat162float(hi));
            g_wt_hi[n * D + k] = hi;
            g_wt_lo[n * D + k] = lo;
        }
        return;
    }
    int i = (b - convB - wB) * 256 + t;
    if (i < E) atomicAdd(&g_hist[row[i]], 1);
    if (i < nsamp) atomicMax(&g_winner[nodes[i]], i + 1);   // 0 = empty
}

// ===== single-kernel scan: each block sums its own prefix (G~25, cheap) ======
__global__ __launch_bounds__(SCAN_TPB) void k_scan(int n, int E) {
    __shared__ int sred[SCAN_TPB / 32];
    __shared__ int ws[SCAN_TPB / 32];
    int t = threadIdx.x, lane = t & 31, w = t >> 5;
    int tileStart = blockIdx.x * SCAN_EPB;

    // phase 1: prefix sum of all preceding tiles
    int ps = 0;
    for (int i = t; i < tileStart; i += SCAN_TPB) ps += g_hist[i];
#pragma unroll
    for (int o = 16; o > 0; o >>= 1) ps += __shfl_xor_sync(0xffffffff, ps, o);
    if (lane == 0) sred[w] = ps;

    // phase 2: local tile loads + warp scan (also zero cursor)
    int base = tileStart + t * 8;
    int v[8], sum = 0;
#pragma unroll
    for (int j = 0; j < 8; j++) {
        int idx = base + j;
        v[j] = (idx < n) ? g_hist[idx] : 0;
        if (idx < n) g_cursor[idx] = 0;
        sum += v[j];
    }
    int x = sum;
#pragma unroll
    for (int o = 1; o < 32; o <<= 1) {
        int y = __shfl_up_sync(0xffffffff, x, o);
        if (lane >= o) x += y;
    }
    if (lane == 31) ws[w] = x;
    __syncthreads();
    if (t == 0) {
        int total = 0;
#pragma unroll
        for (int i = 0; i < SCAN_TPB / 32; i++) total += sred[i];
        int r = total;
#pragma unroll
        for (int i = 0; i < SCAN_TPB / 32; i++) { int q = ws[i]; ws[i] = r; r += q; }
    }
    __syncthreads();
    int run = ws[w] + (x - sum);
#pragma unroll
    for (int j = 0; j < 8; j++) {
        int idx = base + j;
        if (idx < n) g_rowStart[idx] = run;
        run += v[j];
    }
    if (blockIdx.x == 0 && t == 0) g_rowStart[n] = E;
}

// ============ scatter edges into row-sorted order (+ zero hist) ==============
__global__ void k_scatter(const int* __restrict__ row, const int* __restrict__ col,
                          const float* __restrict__ val, int E, int nsamp) {
    int i = blockIdx.x * blockDim.x + threadIdx.x;
    if (i < nsamp) g_hist[i] = 0;               // clean for next call
    if (i < E) {
        int r = row[i];
        int p = g_rowStart[r] + atomicAdd(&g_cursor[r], 1);
        int2 e;
        e.x = col[i];
        e.y = __float_as_int(val[i]);
        g_edge[p] = e;
    }
}

// ====== fused SpMM (warp-per-row, 16B gathers, 8-edge unroll) + decay ========
__global__ __launch_bounds__(256) void k_spmm_decay(
    const int* __restrict__ nodes,
    const float4* __restrict__ y4, float4* __restrict__ newY4,
    int nsamp, int ntotal, int spmmB, int decayB) {
    int b = blockIdx.x;
    int t = threadIdx.x;
    int mn = min(spmmB, decayB);
    int nInter = 2 * mn;
    int type, piece;
    if (b < nInter) { type = b & 1; piece = b >> 1; }
    else { type = (spmmB > decayB) ? 0 : 1; piece = mn + (b - nInter); }

    if (type == 1) {
        long long total = (long long)ntotal * D4;
        long long i0 = (long long)piece * 1024 + t;
#pragma unroll
        for (int j = 0; j < 4; j++) {
            long long i = i0 + j * 256;
            if (i < total) {
                int rrow = (int)(i >> 6);
                if (g_winner[rrow] == 0) {
                    float4 v = y4[i];
                    v.x *= 0.9f; v.y *= 0.9f; v.z *= 0.9f; v.w *= 0.9f;
                    newY4[i] = v;
                }
            }
        }
        return;
    }

    // SpMM: one warp per row, lane owns 8 bf16 (one uint4) of the row
    int warp = t >> 5, lane = t & 31;
    int r = piece * 8 + warp;
    if (r >= nsamp) return;
    int e = g_rowStart[r];
    int end = g_rowStart[r + 1];
    const uint4* xb = (const uint4*)g_xbf;
    float acc[8];
#pragma unroll
    for (int q = 0; q < 8; q++) acc[q] = 0.f;

#pragma unroll 1
    for (; e + 8 <= end; e += 8) {
        uint4 u[8];
        float vv[8];
#pragma unroll
        for (int j = 0; j < 8; j++) {
            int2 ed = g_edge[e + j];
            vv[j] = __int_as_float(ed.y);
            u[j] = xb[(size_t)ed.x * D16 + lane];
        }
#pragma unroll
        for (int j = 0; j < 8; j++) {
            float2 p0 = __bfloat1622float2(*(__nv_bfloat162*)&u[j].x);
            float2 p1 = __bfloat1622float2(*(__nv_bfloat162*)&u[j].y);
            float2 p2 = __bfloat1622float2(*(__nv_bfloat162*)&u[j].z);
            float2 p3 = __bfloat1622float2(*(__nv_bfloat162*)&u[j].w);
            float v = vv[j];
            acc[0] = fmaf(v, p0.x, acc[0]); acc[1] = fmaf(v, p0.y, acc[1]);
            acc[2] = fmaf(v, p1.x, acc[2]); acc[3] = fmaf(v, p1.y, acc[3]);
            acc[4] = fmaf(v, p2.x, acc[4]); acc[5] = fmaf(v, p2.y, acc[5]);
            acc[6] = fmaf(v, p3.x, acc[6]); acc[7] = fmaf(v, p3.y, acc[7]);
        }
    }
    for (; e < end; e++) {
        int2 ed = g_edge[e];
        float v = __int_as_float(ed.y);
        uint4 u = xb[(size_t)ed.x * D16 + lane];
        float2 p0 = __bfloat1622float2(*(__nv_bfloat162*)&u.x);
        float2 p1 = __bfloat1622float2(*(__nv_bfloat162*)&u.y);
        float2 p2 = __bfloat1622float2(*(__nv_bfloat162*)&u.z);
        float2 p3 = __bfloat1622float2(*(__nv_bfloat162*)&u.w);
        acc[0] = fmaf(v, p0.x, acc[0]); acc[1] = fmaf(v, p0.y, acc[1]);
        acc[2] = fmaf(v, p1.x, acc[2]); acc[3] = fmaf(v, p1.y, acc[3]);
        acc[4] = fmaf(v, p2.x, acc[4]); acc[5] = fmaf(v, p2.y, acc[5]);
        acc[6] = fmaf(v, p3.x, acc[6]); acc[7] = fmaf(v, p3.y, acc[7]);
    }

    int node = nodes[r];
    float4 y0 = y4[(size_t)node * D4 + lane * 2];
    float4 y1 = y4[(size_t)node * D4 + lane * 2 + 1];
    float g[8];
    g[0] = fmaf(0.1f, acc[0], 0.9f * y0.x);
    g[1] = fmaf(0.1f, acc[1], 0.9f * y0.y);
    g[2] = fmaf(0.1f, acc[2], 0.9f * y0.z);
    g[3] = fmaf(0.1f, acc[3], 0.9f * y0.w);
    g[4] = fmaf(0.1f, acc[4], 0.9f * y1.x);
    g[5] = fmaf(0.1f, acc[5], 0.9f * y1.y);
    g[6] = fmaf(0.1f, acc[6], 0.9f * y1.z);
    g[7] = fmaf(0.1f, acc[7], 0.9f * y1.w);

    uint4 uh, ul;
    {
        __nv_bfloat16 h[8], l[8];
#pragma unroll
        for (int q = 0; q < 8; q++) {
            h[q] = __float2bfloat16_rn(g[q]);
            l[q] = __float2bfloat16_rn(g[q] - __bfloat162float(h[q]));
        }
        __nv_bfloat162 a0 = __halves2bfloat162(h[0], h[1]);
        __nv_bfloat162 a1 = __halves2bfloat162(h[2], h[3]);
        __nv_bfloat162 a2 = __halves2bfloat162(h[4], h[5]);
        __nv_bfloat162 a3 = __halves2bfloat162(h[6], h[7]);
        uh.x = *(uint32_t*)&a0; uh.y = *(uint32_t*)&a1;
        uh.z = *(uint32_t*)&a2; uh.w = *(uint32_t*)&a3;
        a0 = __halves2bfloat162(l[0], l[1]);
        a1 = __halves2bfloat162(l[2], l[3]);
        a2 = __halves2bfloat162(l[4], l[5]);
        a3 = __halves2bfloat162(l[6], l[7]);
        ul.x = *(uint32_t*)&a0; ul.y = *(uint32_t*)&a1;
        ul.z = *(uint32_t*)&a2; ul.w = *(uint32_t*)&a3;
    }
    ((uint4*)g_feat_hi)[(size_t)r * D16 + lane] = uh;
    ((uint4*)g_feat_lo)[(size_t)r * D16 + lane] = ul;
    if (g_winner[node] == r + 1) {
        newY4[(size_t)node * D4 + lane * 2]     = make_float4(g[0], g[1], g[2], g[3]);
        newY4[(size_t)node * D4 + lane * 2 + 1] = make_float4(g[4], g[5], g[6], g[7]);
    }
}

// ========== HMMA GEMM m16n8k16 bf16 3-term split, reg-prefetch ===============
#define AST 24
#define SM_A_HI 0
#define SM_A_LO 3072
#define SM_B_HI 6144
#define SM_B_LO 18432
#define SM_GEMM_TOTAL 30720
#define EP_SUM  0
#define EP_SSQ  2048
#define EP_MEAN 4096
#define EP_RSTD 4352

__device__ __forceinline__ void mma_bf16(float* c, uint32_t a0, uint32_t a1,
                                         uint32_t a2, uint32_t a3,
                                         uint32_t b0, uint32_t b1) {
    asm volatile(
        "mma.sync.aligned.m16n8k16.row.col.f32.bf16.bf16.f32 "
        "{%0,%1,%2,%3}, {%4,%5,%6,%7}, {%8,%9}, {%0,%1,%2,%3};"
        : "+f"(c[0]), "+f"(c[1]), "+f"(c[2]), "+f"(c[3])
        : "r"(a0), "r"(a1), "r"(a2), "r"(a3), "r"(b0), "r"(b1));
}

__global__ __launch_bounds__(256) void k_gemm_mma(
    const float* __restrict__ bvec, const float* __restrict__ scale,
    const float* __restrict__ offset, float* __restrict__ out,
    int nsamp, int ntotal) {
    __shared__ char sm[SM_GEMM_TOTAL];
    int t = threadIdx.x;
    int warp = t >> 5, lane = t & 31;
    int lq = lane >> 2, lc = lane & 3;
    int wN = warp * 32;
    int rowBase = blockIdx.x * 64;

    float acc[4][4][4];
#pragma unroll
    for (int i = 0; i < 4; i++)
#pragma unroll
        for (int j = 0; j < 4; j++)
#pragma unroll
            for (int q = 0; q < 4; q++) acc[i][j][q] = 0.f;

    int arow = t >> 2, ac4 = t & 3;
    int agrow = rowBase + arow;

    // prefetch registers
    uint2 pAh, pAl, pBh[4], pBl[4];
    {
        pAh = make_uint2(0u, 0u); pAl = make_uint2(0u, 0u);
        if (agrow < nsamp) {
            pAh = *(const uint2*)&g_feat_hi[(size_t)agrow * D + ac4 * 4];
            pAl = *(const uint2*)&g_feat_lo[(size_t)agrow * D + ac4 * 4];
        }
#pragma unroll
        for (int j = 0; j < 4; j++) {
            int i = t + j * 256;
            int n = i >> 2, c4 = i & 3;
            pBh[j] = *(const uint2*)&g_wt_hi[(size_t)n * D + c4 * 4];
            pBl[j] = *(const uint2*)&g_wt_lo[(size_t)n * D + c4 * 4];
        }
    }

    for (int kc = 0; kc < 16; kc++) {
        // commit prefetched tile to smem
        *(uint2*)(sm + SM_A_HI + (arow * AST + ac4 * 4) * 2) = pAh;
        *(uint2*)(sm + SM_A_LO + (arow * AST + ac4 * 4) * 2) = pAl;
#pragma unroll
        for (int j = 0; j < 4; j++) {
            int i = t + j * 256;
            int n = i >> 2, c4 = i & 3;
            *(uint2*)(sm + SM_B_HI + (n * AST + c4 * 4) * 2) = pBh[j];
            *(uint2*)(sm + SM_B_LO + (n * AST + c4 * 4) * 2) = pBl[j];
        }
        __syncthreads();

        // issue next tile loads (overlap with mma below)
        if (kc < 15) {
            int k0 = (kc + 1) * 16;
            pAh = make_uint2(0u, 0u); pAl = make_uint2(0u, 0u);
            if (agrow < nsamp) {
                pAh = *(const uint2*)&g_feat_hi[(size_t)agrow * D + k0 + ac4 * 4];
                pAl = *(const uint2*)&g_feat_lo[(size_t)agrow * D + k0 + ac4 * 4];
            }
#pragma unroll
            for (int j = 0; j < 4; j++) {
                int i = t + j * 256;
                int n = i >> 2, c4 = i & 3;
                pBh[j] = *(const uint2*)&g_wt_hi[(size_t)n * D + k0 + c4 * 4];
                pBl[j] = *(const uint2*)&g_wt_lo[(size_t)n * D + k0 + c4 * 4];
            }
        }

        uint32_t bh[4][2], bl[4][2];
#pragma unroll
        for (int nf = 0; nf < 4; nf++) {
            int n = wN + nf * 8 + lq;
            bh[nf][0] = *(uint32_t*)(sm + SM_B_HI + (n * AST + lc * 2) * 2);
            bh[nf][1] = *(uint32_t*)(sm + SM_B_HI + (n * AST + lc * 2 + 8) * 2);
            bl[nf][0] = *(uint32_t*)(sm + SM_B_LO + (n * AST + lc * 2) * 2);
            bl[nf][1] = *(uint32_t*)(sm + SM_B_LO + (n * AST + lc * 2 + 8) * 2);
        }
        {
            uint32_t ah[4][4];
#pragma unroll
            for (int mf = 0; mf < 4; mf++) {
                int r0 = mf * 16 + lq;
                ah[mf][0] = *(uint32_t*)(sm + SM_A_HI + (r0 * AST + lc * 2) * 2);
                ah[mf][1] = *(uint32_t*)(sm + SM_A_HI + ((r0 + 8) * AST + lc * 2) * 2);
                ah[mf][2] = *(uint32_t*)(sm + SM_A_HI + (r0 * AST + lc * 2 + 8) * 2);
                ah[mf][3] = *(uint32_t*)(sm + SM_A_HI + ((r0 + 8) * AST + lc * 2 + 8) * 2);
            }
#pragma unroll
            for (int mf = 0; mf < 4; mf++)
#pragma unroll
                for (int nf = 0; nf < 4; nf++) {
                    mma_bf16(acc[mf][nf], ah[mf][0], ah[mf][1], ah[mf][2], ah[mf][3],
                             bh[nf][0], bh[nf][1]);
                    mma_bf16(acc[mf][nf], ah[mf][0], ah[mf][1], ah[mf][2], ah[mf][3],
                             bl[nf][0], bl[nf][1]);
                }
        }
        {
            uint32_t al[4][4];
#pragma unroll
            for (int mf = 0; mf < 4; mf++) {
                int r0 = mf * 16 + lq;
                al[mf][0] = *(uint32_t*)(sm + SM_A_LO + (r0 * AST + lc * 2) * 2);
                al[mf][1] = *(uint32_t*)(sm + SM_A_LO + ((r0 + 8) * AST + lc * 2) * 2);
                al[mf][2] = *(uint32_t*)(sm + SM_A_LO + (r0 * AST + lc * 2 + 8) * 2);
                al[mf][3] = *(uint32_t*)(sm + SM_A_LO + ((r0 + 8) * AST + lc * 2 + 8) * 2);
            }
#pragma unroll
            for (int mf = 0; mf < 4; mf++)
#pragma unroll
                for (int nf = 0; nf < 4; nf++)
                    mma_bf16(acc[mf][nf], al[mf][0], al[mf][1], al[mf][2], al[mf][3],
                             bh[nf][0], bh[nf][1]);
        }
        __syncthreads();
    }

    // ---- epilogue: bias -> ELU -> cross-warp row reduce -> normalize --------
    float bb[4][2], ss[4][2], oo[4][2];
#pragma unroll
    for (int nf = 0; nf < 4; nf++) {
        int col = wN + nf * 8 + lc * 2;
        bb[nf][0] = bvec[col];   bb[nf][1] = bvec[col + 1];
        ss[nf][0] = scale[col];  ss[nf][1] = scale[col + 1];
        oo[nf][0] = offset[col]; oo[nf][1] = offset[col + 1];
    }

    float rs[4][2], rq[4][2];
#pragma unroll
    for (int mf = 0; mf < 4; mf++) { rs[mf][0] = rs[mf][1] = 0.f; rq[mf][0] = rq[mf][1] = 0.f; }
#pragma unroll
    for (int mf = 0; mf < 4; mf++)
#pragma unroll
        for (int nf = 0; nf < 4; nf++) {
            float v0 = acc[mf][nf][0] + bb[nf][0];
            float v1 = acc[mf][nf][1] + bb[nf][1];
            float v2 = acc[mf][nf][2] + bb[nf][0];
            float v3 = acc[mf][nf][3] + bb[nf][1];
            v0 = (v0 > 0.f) ? v0 : expm1f(v0);
            v1 = (v1 > 0.f) ? v1 : expm1f(v1);
            v2 = (v2 > 0.f) ? v2 : expm1f(v2);
            v3 = (v3 > 0.f) ? v3 : expm1f(v3);
            acc[mf][nf][0] = v0; acc[mf][nf][1] = v1;
            acc[mf][nf][2] = v2; acc[mf][nf][3] = v3;
            rs[mf][0] += v0 + v1; rq[mf][0] += v0 * v0 + v1 * v1;
            rs[mf][1] += v2 + v3; rq[mf][1] += v2 * v2 + v3 * v3;
        }
#pragma unroll
    for (int mf = 0; mf < 4; mf++)
#pragma unroll
        for (int h = 0; h < 2; h++) {
            rs[mf][h] += __shfl_xor_sync(0xffffffff, rs[mf][h], 1);
            rs[mf][h] += __shfl_xor_sync(0xffffffff, rs[mf][h], 2);
            rq[mf][h] += __shfl_xor_sync(0xffffffff, rq[mf][h], 1);
            rq[mf][h] += __shfl_xor_sync(0xffffffff, rq[mf][h], 2);
        }
    __syncthreads();
    float* rowsum = (float*)(sm + EP_SUM);
    float* rowssq = (float*)(sm + EP_SSQ);
    if (lc == 0) {
#pragma unroll
        for (int mf = 0; mf < 4; mf++) {
            rowsum[(mf * 16 + lq) * 8 + warp]     = rs[mf][0];
            rowssq[(mf * 16 + lq) * 8 + warp]     = rq[mf][0];
            rowsum[(mf * 16 + 8 + lq) * 8 + warp] = rs[mf][1];
            rowssq[(mf * 16 + 8 + lq) * 8 + warp] = rq[mf][1];
        }
    }
    __syncthreads();
    float* meanA = (float*)(sm + EP_MEAN);
    float* rstdA = (float*)(sm + EP_RSTD);
    if (t < 64) {
        float s = 0.f, q = 0.f;
#pragma unroll
        for (int w = 0; w < 8; w++) { s += rowsum[t * 8 + w]; q += rowssq[t * 8 + w]; }
        float mean = s * (1.f / 256.f);
        float var  = q * (1.f / 256.f) - mean * mean + 1e-9f;
        meanA[t] = mean;
        rstdA[t] = rsqrtf(var);
    }
    __syncthreads();

#pragma unroll
    for (int mf = 0; mf < 4; mf++) {
        int rl = mf * 16 + lq;
        int rh = rl + 8;
        float mL = meanA[rl], rL = rstdA[rl];
        float mH = meanA[rh], rH = rstdA[rh];
        int gl = rowBase + rl, gh = rowBase + rh;
#pragma unroll
        for (int nf = 0; nf < 4; nf++) {
            int col = wN + nf * 8 + lc * 2;
            if (gl < nsamp) {
                float2 p;
                p.x = (acc[mf][nf][0] - mL) * ss[nf][0] * rL + oo[nf][0];
                p.y = (acc[mf][nf][1] - mL) * ss[nf][1] * rL + oo[nf][1];
                *(float2*)(out + (size_t)gl * D + col) = p;
            }
            if (gh < nsamp) {
                float2 p;
                p.x = (acc[mf][nf][2] - mH) * ss[nf][0] * rH + oo[nf][0];
                p.y = (acc[mf][nf][3] - mH) * ss[nf][1] * rH + oo[nf][1];
                *(float2*)(out + (size_t)gh * D + col) = p;
            }
        }
    }

    // reset winner for next invocation (last kernel in the pipeline)
    for (int gi = blockIdx.x * 256 + t; gi < ntotal; gi += gridDim.x * 256)
        g_winner[gi] = 0;
}

// -----------------------------------------------------------------------------
extern "C" void kernel_launch(void* const* d_in, const int* in_sizes, int n_in,
                              void* d_out, int out_size) {
    const float* x        = (const float*)d_in[0];
    const int*   adj_row  = (const int*)d_in[1];
    const int*   adj_col  = (const int*)d_in[2];
    const float* adj_val  = (const float*)d_in[3];
    const int*   nodes    = (const int*)d_in[4];
    const float* y_buf    = (const float*)d_in[5];
    const float* W        = (const float*)d_in[6];
    const float* b        = (const float*)d_in[7];
    const float* scale    = (const float*)d_in[8];
    const float* offset   = (const float*)d_in[9];

    int E      = in_sizes[1];
    int nsamp  = in_sizes[4];
    int nsrc   = in_sizes[0] / D;
    int ntotal = in_sizes[5] / D;

    float* out  = (float*)d_out;
    float* newY = out + (size_t)nsamp * D;

    int G = (nsamp + SCAN_EPB - 1) / SCAN_EPB;
    int spmmB  = (nsamp + 7) / 8;
    int decayB = (ntotal * D4 + 1023) / 1024;
    int convB  = (nsrc * D4 + 1023) / 1024;
    int wB     = (D * D + 255) / 256;
    int histB  = (E + 255) / 256;

    k_prep<<<convB + wB + histB, 256>>>(x, W, adj_row, E, nodes, nsamp, nsrc, convB, wB);
    k_scan<<<G, SCAN_TPB>>>(nsamp, E);
    k_scatter<<<(E + 255) / 256, 256>>>(adj_row, adj_col, adj_val, E, nsamp);
    k_spmm_decay<<<spmmB + decayB, 256>>>(nodes, (const float4*)y_buf, (float4*)newY,
                                          nsamp, ntotal, spmmB, decayB);
    k_gemm_mma<<<(nsamp + 63) / 64, 256>>>(b, scale, offset, out, nsamp, ntotal);
}